// round 15
// baseline (speedup 1.0000x reference)
#include <cuda_runtime.h>
#include <cuda_fp16.h>
#include <mma.h>
#include <cstdint>

using namespace nvcuda;

#define NB 16
#define NL 8192
#define ND 256
#define NH 4
#define HID 128
#define QKV_LD 384

typedef unsigned long long ull;
typedef unsigned int u32;

// ---------------- scratch (device globals; no allocation) ----------------
__device__ float g_Sp[(size_t)NB * NH * 64 * 1024];      // per-CTA partial S (16MB)
__device__ float g_Zp[NB * NH * 64 * 32];                // per-CTA partial Z
__device__ float g_M[NB * HID * ND];                     // M[b]
__device__ half g_W1[256 * 256];                         // Wkv^T fp16 [n][k]
__device__ half g_W3[NB * 256 * 256];                    // N[b]^T fp16 [b][j][i]
__device__ half g_X16[(size_t)NB * NL * 256];            // x fp16 (written by kv GEMM)

// ---------------- helpers ----------------
__device__ __forceinline__ u32 smem_u32(const void* p) {
    u32 a;
    asm("{ .reg .u64 t; cvta.to.shared.u64 t, %1; cvt.u32.u64 %0, t; }" : "=r"(a) : "l"(p));
    return a;
}
__device__ __forceinline__ void cp16(u32 dst, const void* src) {
    asm volatile("cp.async.cg.shared.global [%0], [%1], 16;" :: "r"(dst), "l"(src) : "memory");
}
__device__ __forceinline__ void cp_commit() { asm volatile("cp.async.commit_group;" ::: "memory"); }
template<int N> __device__ __forceinline__ void cp_wait() {
    asm volatile("cp.async.wait_group %0;" :: "n"(N) : "memory");
}
__device__ __forceinline__ void sts64(u32 addr, u32 a, u32 b) {
    asm volatile("st.shared.v2.b32 [%0], {%1,%2};" :: "r"(addr), "r"(a), "r"(b) : "memory");
}
__device__ __forceinline__ ull pk2(float x, float y) {
    ull r; asm("mov.b64 %0, {%1,%2};" : "=l"(r) : "f"(x), "f"(y)); return r;
}
__device__ __forceinline__ ull fma2(ull a, ull b, ull c) {
    ull d; asm("fma.rn.f32x2 %0, %1, %2, %3;" : "=l"(d) : "l"(a), "l"(b), "l"(c)); return d;
}
__device__ __forceinline__ void upk2(ull v, float& a, float& b) {
    asm("mov.b64 {%0,%1}, %2;" : "=f"(a), "=f"(b) : "l"(v));
}
__device__ __forceinline__ u32 pkh2(half a, half b) {
    half2 t = __halves2half2(a, b);
    return *reinterpret_cast<u32*>(&t);
}

// SMEM stage layout: k-chunk 64, row stride 72 fp16 = 144B (9x16B -> LDSM conflict-free)
#define RS 72
#define O_A 0
#define O_B 18432
#define SZ_ST 55296

// kv kernel smem: 3 stages (165888) overlapped by epilogue layout:
//   Cs f32[128][256] @0 (131072), Ch fp16[128][264] @131072 (67584), zp @198656 (4096)
#define CH_OFF 131072
#define ZP_OFF 198656
#define CHS 264
#define SMEM_KV 202752

// out kernel: 4 stages fully prefetched
#define SMEM_OUT 221184

// =====================================================================
// kv GEMM (512 threads): kv[128-tile x 256] = x @ W1^T (fp16 single pass).
// Also writes x16. Epilogue: exp + Z (fp32) + S via wmma (16 warps).
// =====================================================================
__global__ void __launch_bounds__(512) mma_kv(
    const float* __restrict__ A, const half* __restrict__ B, half* __restrict__ X16)
{
    extern __shared__ unsigned char smem_raw[];
    float* Cs = reinterpret_cast<float*>(smem_raw);
    half* Ch = reinterpret_cast<half*>(smem_raw + CH_OFF);
    float* zp = reinterpret_cast<float*>(smem_raw + ZP_OFF);
    const u32 sbase = smem_u32(smem_raw);

    const int tid = threadIdx.x;
    const int wid = tid >> 5;
    const int wm = wid >> 2;        // 0..3 (rows, 32 each)
    const int wn = wid & 3;         // 0..3 (cols, 64 each)
    const int b = blockIdx.y;
    const int l0 = blockIdx.x * 128;

    const float* AB = A + (size_t)b * NL * 256 + (size_t)l0 * 256;
    half* XB = X16 + (size_t)b * NL * 256 + (size_t)l0 * 256;

    wmma::fragment<wmma::accumulator, 16, 16, 16, float> acc[2][4];
#pragma unroll
    for (int mi = 0; mi < 2; mi++)
#pragma unroll
        for (int ni = 0; ni < 4; ni++) wmma::fill_fragment(acc[mi][ni], 0.0f);

    float4 areg[4];

    auto load_A = [&](int it) {
        const int k0 = it * 64;
#pragma unroll
        for (int i = 0; i < 4; i++) {
            int idx = i * 512 + tid;
            int row = idx >> 4, c4 = idx & 15;
            areg[i] = __ldg((const float4*)(AB + (size_t)row * 256 + k0 + c4 * 4));
        }
    };
    auto sts_A = [&](int st, int it) {
        const u32 hb = sbase + st * SZ_ST + O_A;
        const int k0 = it * 64;
#pragma unroll
        for (int i = 0; i < 4; i++) {
            int idx = i * 512 + tid;
            int row = idx >> 4, c4 = idx & 15;
            float4 v = areg[i];
            u32 p0 = pkh2(__float2half_rn(v.x), __float2half_rn(v.y));
            u32 p1 = pkh2(__float2half_rn(v.z), __float2half_rn(v.w));
            sts64(hb + (u32)(row * 144 + c4 * 8), p0, p1);
            *(uint2*)(XB + (size_t)row * 256 + k0 + c4 * 4) = make_uint2(p0, p1);
        }
    };
    auto issue_B = [&](int it, int st) {
        const int k0 = it * 64;
        const u32 s0 = sbase + st * SZ_ST + O_B;
#pragma unroll
        for (int i = 0; i < 4; i++) {
            int idx = tid + i * 512;
            int n = idx >> 3, seg = idx & 7;
            cp16(s0 + (u32)(n * 144 + seg * 16), B + (size_t)n * 256 + k0 + seg * 8);
        }
        cp_commit();
    };

    load_A(0);
    sts_A(0, 0);
    load_A(1);
    issue_B(0, 0);
    issue_B(1, 1);

    for (int it = 0; it < 4; it++) {
        const int st = it % 3;
        if (it < 3) cp_wait<1>(); else cp_wait<0>();
        __syncthreads();
        if (it < 2) issue_B(it + 2, (it + 2) % 3);

        const half* Ah = (const half*)(smem_raw + st * SZ_ST + O_A);
        const half* Bs = (const half*)(smem_raw + st * SZ_ST + O_B);

#pragma unroll
        for (int kk = 0; kk < 4; kk++) {
            wmma::fragment<wmma::matrix_a, 16, 16, 16, half, wmma::row_major> ah[2];
            wmma::fragment<wmma::matrix_b, 16, 16, 16, half, wmma::col_major> bf[4];
#pragma unroll
            for (int mi = 0; mi < 2; mi++)
                wmma::load_matrix_sync(ah[mi], Ah + (wm * 32 + mi * 16) * RS + kk * 16, RS);
#pragma unroll
            for (int ni = 0; ni < 4; ni++)
                wmma::load_matrix_sync(bf[ni], Bs + (wn * 64 + ni * 16) * RS + kk * 16, RS);
#pragma unroll
            for (int mi = 0; mi < 2; mi++)
#pragma unroll
                for (int ni = 0; ni < 4; ni++)
                    wmma::mma_sync(acc[mi][ni], ah[mi], bf[ni], acc[mi][ni]);
        }
        if (it < 3) {
            sts_A((it + 1) % 3, it + 1);
            if (it < 2) load_A(it + 2);
        }
    }
    __syncthreads();

    // ---- stage buffers dead; Cs[128][256] aliases them
#pragma unroll
    for (int mi = 0; mi < 2; mi++)
#pragma unroll
        for (int ni = 0; ni < 4; ni++)
            wmma::store_matrix_sync(Cs + (size_t)(wm * 32 + mi * 16) * 256 + wn * 64 + ni * 16,
                                    acc[mi][ni], 256, wmma::mem_row_major);
    __syncthreads();

    // ---- convert pass: exp on K half, fp16 into Ch, Z partials (fp32)
    {
        const int c4 = tid & 63;
        const int rg = tid >> 6;
        float z0 = 0.f, z1 = 0.f, z2 = 0.f, z3 = 0.f;
        const bool isK = (c4 < 32);
#pragma unroll
        for (int i = 0; i < 16; i++) {
            int row = rg + i * 8;
            float4 v = *(const float4*)(Cs + (size_t)row * 256 + c4 * 4);
            if (isK) {
                v.x = __expf(v.x); v.y = __expf(v.y);
                v.z = __expf(v.z); v.w = __expf(v.w);
                z0 += v.x; z1 += v.y; z2 += v.z; z3 += v.w;
            }
            u32 p0 = pkh2(__float2half_rn(v.x), __float2half_rn(v.y));
            u32 p1 = pkh2(__float2half_rn(v.z), __float2half_rn(v.w));
            *(uint2*)(Ch + (size_t)row * CHS + c4 * 4) = make_uint2(p0, p1);
        }
        if (isK)
            *(float4*)(zp + rg * 128 + c4 * 4) = make_float4(z0, z1, z2, z3);
    }
    __syncthreads();

    // ---- Z final (threads 0..127)
    if (tid < 128) {
        float z = 0.f;
#pragma unroll
        for (int g = 0; g < 8; g++) z += zp[g * 128 + tid];
        int h = tid >> 5, d = tid & 31;
        g_Zp[((size_t)(b * 4 + h) * 64 + blockIdx.x) * 32 + d] = z;
    }

    // ---- S via wmma: 16 warps, one 16x16 S tile each
    {
        const int h = wid >> 2, dh = (wid >> 1) & 1, eh = wid & 1;
        wmma::fragment<wmma::accumulator, 16, 16, 16, float> sacc;
        wmma::fill_fragment(sacc, 0.0f);
        const half* ChA = Ch + h * 32 + dh * 16;
        const half* ChB = Ch + 128 + h * 32 + eh * 16;
#pragma unroll
        for (int kk = 0; kk < 8; kk++) {
            wmma::fragment<wmma::matrix_a, 16, 16, 16, half, wmma::col_major> af;
            wmma::fragment<wmma::matrix_b, 16, 16, 16, half, wmma::row_major> bf;
            wmma::load_matrix_sync(af, ChA + (size_t)kk * 16 * CHS, CHS);
            wmma::load_matrix_sync(bf, ChB + (size_t)kk * 16 * CHS, CHS);
            wmma::mma_sync(sacc, af, bf, sacc);
        }
        float* Sp = g_Sp + ((size_t)(b * 4 + h) * 64 + blockIdx.x) * 1024
                  + dh * 16 * 32 + eh * 16;
        wmma::store_matrix_sync(Sp, sacc, 32, wmma::mem_row_major);
    }
}

// =====================================================================
// out GEMM (512 threads): out[128-tile x 256] = x16 @ W3^T + bias.
// Bias folded into accumulators via ones x bias MMA; accumulators stored
// DIRECTLY to global (no smem round-trip).
// =====================================================================
__global__ void __launch_bounds__(512) mma_out(
    const half* __restrict__ A16, const half* __restrict__ B,
    float* __restrict__ C, const float* __restrict__ bias)
{
    extern __shared__ unsigned char smem_raw[];
    const u32 sbase = smem_u32(smem_raw);
    __shared__ half sOnes[256];        // A[i][k] = (k==0)
    __shared__ half sBb[4096];         // [n][k] = (k==0) ? bias[n] : 0

    const int tid = threadIdx.x;
    const int wid = tid >> 5;
    const int wm = wid >> 2;
    const int wn = wid & 3;
    const int b = blockIdx.y;
    const int l0 = blockIdx.x * 128;

    const half* AB = A16 + (size_t)b * NL * 256 + (size_t)l0 * 256;
    const half* BB = B + (size_t)b * 65536;

    // fill bias helper tiles
    if (tid < 256) sOnes[tid] = ((tid & 15) == 0) ? __float2half(1.0f) : __float2half(0.0f);
#pragma unroll
    for (int i = 0; i < 8; i++) {
        int idx = tid * 8 + i;
        if (idx < 4096) {
            int n = idx >> 4, k = idx & 15;
            sBb[idx] = (k == 0) ? __float2half_rn(__ldg(bias + n)) : __float2half(0.0f);
        }
    }

    // prefetch all 4 chunks
#pragma unroll
    for (int it = 0; it < 4; it++) {
        const int k0 = it * 64;
        const u32 s0 = sbase + it * SZ_ST;
#pragma unroll
        for (int i = 0; i < 2; i++) {
            int idx = tid + i * 512;
            int row = idx >> 3, seg = idx & 7;
            cp16(s0 + O_A + (u32)(row * 144 + seg * 16), AB + (size_t)row * 256 + k0 + seg * 8);
        }
#pragma unroll
        for (int i = 0; i < 4; i++) {
            int idx = tid + i * 512;
            int n = idx >> 3, seg = idx & 7;
            cp16(s0 + O_B + (u32)(n * 144 + seg * 16), BB + (size_t)n * 256 + k0 + seg * 8);
        }
        cp_commit();
    }
    __syncthreads();   // sOnes/sBb visible

    // init accumulators with bias rows: acc = ones_col0 @ bias_row0
    wmma::fragment<wmma::accumulator, 16, 16, 16, float> acc[2][4];
    {
        wmma::fragment<wmma::matrix_a, 16, 16, 16, half, wmma::row_major> a1;
        wmma::load_matrix_sync(a1, sOnes, 16);
#pragma unroll
        for (int ni = 0; ni < 4; ni++) {
            wmma::fragment<wmma::matrix_b, 16, 16, 16, half, wmma::col_major> bb;
            wmma::load_matrix_sync(bb, sBb + (wn * 64 + ni * 16) * 16, 16);
            wmma::fill_fragment(acc[0][ni], 0.0f);
            wmma::mma_sync(acc[0][ni], a1, bb, acc[0][ni]);
            acc[1][ni] = acc[0][ni];
        }
    }

    for (int it = 0; it < 4; it++) {
        if (it == 0) cp_wait<3>();
        else if (it == 1) cp_wait<2>();
        else if (it == 2) cp_wait<1>();
        else cp_wait<0>();
        __syncthreads();

        const half* Ah = (const half*)(smem_raw + it * SZ_ST + O_A);
        const half* Bs = (const half*)(smem_raw + it * SZ_ST + O_B);

#pragma unroll
        for (int kk = 0; kk < 4; kk++) {
            wmma::fragment<wmma::matrix_a, 16, 16, 16, half, wmma::row_major> ah[2];
            wmma::fragment<wmma::matrix_b, 16, 16, 16, half, wmma::col_major> bf[4];
#pragma unroll
            for (int mi = 0; mi < 2; mi++)
                wmma::load_matrix_sync(ah[mi], Ah + (wm * 32 + mi * 16) * RS + kk * 16, RS);
#pragma unroll
            for (int ni = 0; ni < 4; ni++)
                wmma::load_matrix_sync(bf[ni], Bs + (wn * 64 + ni * 16) * RS + kk * 16, RS);
#pragma unroll
            for (int mi = 0; mi < 2; mi++)
#pragma unroll
                for (int ni = 0; ni < 4; ni++)
                    wmma::mma_sync(acc[mi][ni], ah[mi], bf[ni], acc[mi][ni]);
        }
    }

    // direct store to global (no smem epilogue)
    float* Cb = C + (size_t)b * NL * 256 + (size_t)l0 * 256;
#pragma unroll
    for (int mi = 0; mi < 2; mi++)
#pragma unroll
        for (int ni = 0; ni < 4; ni++)
            wmma::store_matrix_sync(Cb + (size_t)(wm * 32 + mi * 16) * 256 + wn * 64 + ni * 16,
                                    acc[mi][ni], 256, wmma::mem_row_major);
}

// ---------------- prep: Wkv^T fp16 ----------------
__global__ void prep_w1(const float* __restrict__ Wqkv)
{
    const int n = blockIdx.x, k = threadIdx.x;
    g_W1[n * 256 + k] = __float2half_rn(Wqkv[k * QKV_LD + 128 + n]);
}

// ---------------- fused: ctx (reduce partials) + M[b] rows for one head ----------------
__global__ void __launch_bounds__(1024) ctxm_kernel(const float* __restrict__ Wout)
{
    const int b = blockIdx.x, h = blockIdx.y;
    const int t = threadIdx.x;
    const int d = t >> 5, e = t & 31;
    __shared__ float ctx_sm[1024];
    __shared__ float zs[32];

    const float* Sp = g_Sp + (size_t)(b * 4 + h) * 64 * 1024;
    float s = 0.f;
#pragma unroll
    for (int sp = 0; sp < 64; sp++) s += Sp[sp * 1024 + t];
    if (e == 0) {
        const float* Zp = g_Zp + (size_t)(b * 4 + h) * 64 * 32;
        float zz = 0.f;
#pragma unroll
        for (int sp = 0; sp < 64; sp++) zz += Zp[sp * 32 + d];
        zs[d] = zz;
    }
    __syncthreads();
    ctx_sm[t] = s / zs[d];
    __syncthreads();

    const int j = t & 255, dg = t >> 8;
    float w[32];
#pragma unroll
    for (int e2 = 0; e2 < 32; e2++) w[e2] = Wout[(h * 32 + e2) * 256 + j];
    float* Mb = g_M + (size_t)b * HID * ND;
#pragma unroll
    for (int dd = 0; dd < 8; dd++) {
        int d2 = dg * 8 + dd;
        float a = 0.f;
#pragma unroll
        for (int e2 = 0; e2 < 32; e2++) a += ctx_sm[d2 * 32 + e2] * w[e2];
        Mb[(h * 32 + d2) * 256 + j] = a;
    }
}

// ---------------- small fp32 GEMM, 32x64 tiles (512 CTAs): writes N^T fp16 ----------------
__global__ void __launch_bounds__(256) gemm_nt(
    const float* __restrict__ A, int lda,        // Wqkv (q part), rows = out dim i
    const float* __restrict__ B, int ldb,        // M[b], [128][256]
    half* __restrict__ W3, float scale)
{
    const int b = blockIdx.z;
    const int r0 = blockIdx.y * 32;              // i tile (32)
    const int n0 = blockIdx.x * 64;              // j tile (64)
    A += (size_t)r0 * lda;
    B += (size_t)b * HID * ND;

    __shared__ float As[16][32];
    __shared__ float Bs[16][64];
    const int tid = threadIdx.x;
    const int tx = tid & 15;                     // j group (4 cols)
    const int ty = tid >> 4;                     // i pair (2 rows)

    ull acc[2][2];
    acc[0][0] = acc[0][1] = acc[1][0] = acc[1][1] = 0ULL;

    for (int k0 = 0; k0 < HID; k0 += 16) {
        if (tid < 128) {                         // A chunk: 32x16 = 128 float4
            int row = tid >> 2, c4 = (tid & 3) * 4;
            float4 av = *(const float4*)(A + (size_t)row * lda + k0 + c4);
            As[c4 + 0][row] = av.x; As[c4 + 1][row] = av.y;
            As[c4 + 2][row] = av.z; As[c4 + 3][row] = av.w;
        }
        {                                        // B chunk: 16x64 = 256 float4
            int brow = tid >> 4, bc = (tid & 15) * 4;
            *(float4*)(&Bs[brow][bc]) = *(const float4*)(B + (size_t)(k0 + brow) * ldb + n0 + bc);
        }
        __syncthreads();
#pragma unroll
        for (int kk = 0; kk < 16; kk++) {
            float2 a0 = *(const float2*)(&As[kk][ty * 2]);
            float4 b0 = *(const float4*)(&Bs[kk][tx * 4]);
            ull bp0 = pk2(b0.x, b0.y), bp1 = pk2(b0.z, b0.w);
            ull ap0 = pk2(a0.x, a0.x), ap1 = pk2(a0.y, a0.y);
            acc[0][0] = fma2(ap0, bp0, acc[0][0]);
            acc[0][1] = fma2(ap0, bp1, acc[0][1]);
            acc[1][0] = fma2(ap1, bp0, acc[1][0]);
            acc[1][1] = fma2(ap1, bp1, acc[1][1]);
        }
        __syncthreads();
    }

    float c[2][4];
#pragma unroll
    for (int m = 0; m < 2; m++) {
        upk2(acc[m][0], c[m][0], c[m][1]);
        upk2(acc[m][1], c[m][2], c[m][3]);
    }
    half* W = W3 + (size_t)b * 65536;
#pragma unroll
    for (int jj = 0; jj < 4; jj++) {
        int j = n0 + tx * 4 + jj;
        half2 p = __halves2half2(__float2half_rn(c[0][jj] * scale),
                                 __float2half_rn(c[1][jj] * scale));
        *(u32*)(W + (size_t)j * 256 + r0 + ty * 2) = *(u32*)&p;
    }
}

// ---------------- launch ----------------
extern "C" void kernel_launch(void* const* d_in, const int* in_sizes, int n_in,
                              void* d_out, int out_size)
{
    const float* x    = (const float*)d_in[0];
    const float* Wqkv = (const float*)d_in[1];
    const float* Wout = (const float*)d_in[2];
    const float* bout = (const float*)d_in[3];
    float* out = (float*)d_out;

    float* Mp;
    half *w1, *w3, *x16;
    cudaGetSymbolAddress((void**)&Mp, g_M);
    cudaGetSymbolAddress((void**)&w1, g_W1);
    cudaGetSymbolAddress((void**)&w3, g_W3);
    cudaGetSymbolAddress((void**)&x16, g_X16);

    cudaFuncSetAttribute(mma_kv, cudaFuncAttributeMaxDynamicSharedMemorySize, SMEM_KV);
    cudaFuncSetAttribute(mma_out, cudaFuncAttributeMaxDynamicSharedMemorySize, SMEM_OUT);

    const float scale = 0.17677669529663687f;

    // 1) Wkv^T fp16
    prep_w1<<<256, 256>>>(Wqkv);

    // 2) kv GEMM + x16 emit + fused exp/S/Z (512 threads)
    mma_kv<<<dim3(64, NB), 512, SMEM_KV>>>(x, w1, x16);

    // 3) fused ctx + M
    ctxm_kernel<<<dim3(NB, NH), 1024>>>(Wout);

    // 4) N^T fp16 = (scale * Wq @ M[b])^T, 32x64 tiles, 512 CTAs
    gemm_nt<<<dim3(4, 8, NB), 256>>>(Wqkv, QKV_LD, Mp, ND, w3, scale);

    // 5) out = x16 @ N[b] + b_out (bias in acc, direct global store)
    mma_out<<<dim3(64, NB), 512, SMEM_OUT>>>(x16, w3, out, bout);
}

// round 16
// speedup vs baseline: 1.4330x; 1.4330x over previous
#include <cuda_runtime.h>
#include <cuda_fp16.h>
#include <mma.h>
#include <cstdint>

using namespace nvcuda;

#define NB 16
#define NL 8192
#define ND 256
#define NH 4
#define HID 128
#define QKV_LD 384

typedef unsigned long long ull;
typedef unsigned int u32;

// ---------------- scratch (device globals; no allocation) ----------------
__device__ float g_Sp[(size_t)NB * NH * 64 * 1024];      // per-CTA partial S (16MB)
__device__ float g_Zp[NB * NH * 64 * 32];                // per-CTA partial Z
__device__ float g_M[NB * HID * ND];                     // M[b]
__device__ half g_W1[256 * 256];                         // Wkv^T fp16 [n][k]
__device__ half g_W3[NB * 256 * 256];                    // N[b]^T fp16 [b][j][i]
__device__ half g_X16[(size_t)NB * NL * 256];            // x fp16 (written by kv GEMM)

// ---------------- helpers ----------------
__device__ __forceinline__ u32 smem_u32(const void* p) {
    u32 a;
    asm("{ .reg .u64 t; cvta.to.shared.u64 t, %1; cvt.u32.u64 %0, t; }" : "=r"(a) : "l"(p));
    return a;
}
__device__ __forceinline__ void cp16(u32 dst, const void* src) {
    asm volatile("cp.async.cg.shared.global [%0], [%1], 16;" :: "r"(dst), "l"(src) : "memory");
}
__device__ __forceinline__ void cp_commit() { asm volatile("cp.async.commit_group;" ::: "memory"); }
template<int N> __device__ __forceinline__ void cp_wait() {
    asm volatile("cp.async.wait_group %0;" :: "n"(N) : "memory");
}
__device__ __forceinline__ void sts64(u32 addr, u32 a, u32 b) {
    asm volatile("st.shared.v2.b32 [%0], {%1,%2};" :: "r"(addr), "r"(a), "r"(b) : "memory");
}
__device__ __forceinline__ ull pk2(float x, float y) {
    ull r; asm("mov.b64 %0, {%1,%2};" : "=l"(r) : "f"(x), "f"(y)); return r;
}
__device__ __forceinline__ ull fma2(ull a, ull b, ull c) {
    ull d; asm("fma.rn.f32x2 %0, %1, %2, %3;" : "=l"(d) : "l"(a), "l"(b), "l"(c)); return d;
}
__device__ __forceinline__ void upk2(ull v, float& a, float& b) {
    asm("mov.b64 {%0,%1}, %2;" : "=f"(a), "=f"(b) : "l"(v));
}
__device__ __forceinline__ u32 pkh2(half a, half b) {
    half2 t = __halves2half2(a, b);
    return *reinterpret_cast<u32*>(&t);
}

// SMEM stage layout: k-chunk 64, row stride 72 fp16 = 144B (9x16B -> LDSM conflict-free)
#define RS 72
#define O_A 0
#define O_B 18432
#define SZ_ST 55296

// kv kernel smem: 3 stages (165888) overlapped by epilogue layout:
//   Cs f32[128][256] @0 (131072), Ch fp16[128][264] @131072 (67584), zp @198656 (4096)
#define CH_OFF 131072
#define ZP_OFF 198656
#define CHS 264
#define SMEM_KV 202752

// out kernel: 4 stages fully prefetched (221184); Cs overlaps dead stages
#define SMEM_OUT 221184

// =====================================================================
// kv GEMM (512 threads): kv[128-tile x 256] = x @ W1^T (fp16 single pass).
// Also writes x16. Epilogue: exp + Z (fp32) + S via wmma (16 warps, one
// 16x16 S tile each).
// =====================================================================
__global__ void __launch_bounds__(512) mma_kv(
    const float* __restrict__ A, const half* __restrict__ B, half* __restrict__ X16)
{
    extern __shared__ unsigned char smem_raw[];
    float* Cs = reinterpret_cast<float*>(smem_raw);
    half* Ch = reinterpret_cast<half*>(smem_raw + CH_OFF);
    float* zp = reinterpret_cast<float*>(smem_raw + ZP_OFF);
    const u32 sbase = smem_u32(smem_raw);

    const int tid = threadIdx.x;
    const int wid = tid >> 5;
    const int wm = wid >> 2;        // 0..3 (rows, 32 each)
    const int wn = wid & 3;         // 0..3 (cols, 64 each)
    const int b = blockIdx.y;
    const int l0 = blockIdx.x * 128;

    const float* AB = A + (size_t)b * NL * 256 + (size_t)l0 * 256;
    half* XB = X16 + (size_t)b * NL * 256 + (size_t)l0 * 256;

    wmma::fragment<wmma::accumulator, 16, 16, 16, float> acc[2][4];
#pragma unroll
    for (int mi = 0; mi < 2; mi++)
#pragma unroll
        for (int ni = 0; ni < 4; ni++) wmma::fill_fragment(acc[mi][ni], 0.0f);

    float4 areg[4];                 // 2048 float4 slots / 512 threads

    auto load_A = [&](int it) {
        const int k0 = it * 64;
#pragma unroll
        for (int i = 0; i < 4; i++) {
            int idx = i * 512 + tid;
            int row = idx >> 4, c4 = idx & 15;
            areg[i] = __ldg((const float4*)(AB + (size_t)row * 256 + k0 + c4 * 4));
        }
    };
    auto sts_A = [&](int st, int it) {
        const u32 hb = sbase + st * SZ_ST + O_A;
        const int k0 = it * 64;
#pragma unroll
        for (int i = 0; i < 4; i++) {
            int idx = i * 512 + tid;
            int row = idx >> 4, c4 = idx & 15;
            float4 v = areg[i];
            u32 p0 = pkh2(__float2half_rn(v.x), __float2half_rn(v.y));
            u32 p1 = pkh2(__float2half_rn(v.z), __float2half_rn(v.w));
            sts64(hb + (u32)(row * 144 + c4 * 8), p0, p1);
            *(uint2*)(XB + (size_t)row * 256 + k0 + c4 * 4) = make_uint2(p0, p1);
        }
    };
    auto issue_B = [&](int it, int st) {
        const int k0 = it * 64;
        const u32 s0 = sbase + st * SZ_ST + O_B;
#pragma unroll
        for (int i = 0; i < 4; i++) {
            int idx = tid + i * 512;
            int n = idx >> 3, seg = idx & 7;
            cp16(s0 + (u32)(n * 144 + seg * 16), B + (size_t)n * 256 + k0 + seg * 8);
        }
        cp_commit();
    };

    load_A(0);
    sts_A(0, 0);
    load_A(1);
    issue_B(0, 0);
    issue_B(1, 1);

    for (int it = 0; it < 4; it++) {
        const int st = it % 3;
        if (it < 3) cp_wait<1>(); else cp_wait<0>();
        __syncthreads();
        if (it < 2) issue_B(it + 2, (it + 2) % 3);

        const half* Ah = (const half*)(smem_raw + st * SZ_ST + O_A);
        const half* Bs = (const half*)(smem_raw + st * SZ_ST + O_B);

#pragma unroll
        for (int kk = 0; kk < 4; kk++) {
            wmma::fragment<wmma::matrix_a, 16, 16, 16, half, wmma::row_major> ah[2];
            wmma::fragment<wmma::matrix_b, 16, 16, 16, half, wmma::col_major> bf[4];
#pragma unroll
            for (int mi = 0; mi < 2; mi++)
                wmma::load_matrix_sync(ah[mi], Ah + (wm * 32 + mi * 16) * RS + kk * 16, RS);
#pragma unroll
            for (int ni = 0; ni < 4; ni++)
                wmma::load_matrix_sync(bf[ni], Bs + (wn * 64 + ni * 16) * RS + kk * 16, RS);
#pragma unroll
            for (int mi = 0; mi < 2; mi++)
#pragma unroll
                for (int ni = 0; ni < 4; ni++)
                    wmma::mma_sync(acc[mi][ni], ah[mi], bf[ni], acc[mi][ni]);
        }
        if (it < 3) {
            sts_A((it + 1) % 3, it + 1);
            if (it < 2) load_A(it + 2);
        }
    }
    __syncthreads();

    // ---- stage buffers dead; Cs[128][256] aliases them
#pragma unroll
    for (int mi = 0; mi < 2; mi++)
#pragma unroll
        for (int ni = 0; ni < 4; ni++)
            wmma::store_matrix_sync(Cs + (size_t)(wm * 32 + mi * 16) * 256 + wn * 64 + ni * 16,
                                    acc[mi][ni], 256, wmma::mem_row_major);
    __syncthreads();

    // ---- convert pass: exp on K half, fp16 into Ch, Z partials (fp32)
    {
        const int c4 = tid & 63;             // column group (4 cols)
        const int rg = tid >> 6;             // row group 0..7
        float z0 = 0.f, z1 = 0.f, z2 = 0.f, z3 = 0.f;
        const bool isK = (c4 < 32);
#pragma unroll
        for (int i = 0; i < 16; i++) {
            int row = rg + i * 8;
            float4 v = *(const float4*)(Cs + (size_t)row * 256 + c4 * 4);
            if (isK) {
                v.x = __expf(v.x); v.y = __expf(v.y);
                v.z = __expf(v.z); v.w = __expf(v.w);
                z0 += v.x; z1 += v.y; z2 += v.z; z3 += v.w;
            }
            u32 p0 = pkh2(__float2half_rn(v.x), __float2half_rn(v.y));
            u32 p1 = pkh2(__float2half_rn(v.z), __float2half_rn(v.w));
            *(uint2*)(Ch + (size_t)row * CHS + c4 * 4) = make_uint2(p0, p1);
        }
        if (isK)
            *(float4*)(zp + rg * 128 + c4 * 4) = make_float4(z0, z1, z2, z3);
    }
    __syncthreads();

    // ---- Z final (threads 0..127)
    if (tid < 128) {
        float z = 0.f;
#pragma unroll
        for (int g = 0; g < 8; g++) z += zp[g * 128 + tid];
        int h = tid >> 5, d = tid & 31;
        g_Zp[((size_t)(b * 4 + h) * 64 + blockIdx.x) * 32 + d] = z;
    }

    // ---- S via wmma: 16 warps, one 16x16 S tile each
    {
        const int h = wid >> 2, dh = (wid >> 1) & 1, eh = wid & 1;
        wmma::fragment<wmma::accumulator, 16, 16, 16, float> sacc;
        wmma::fill_fragment(sacc, 0.0f);
        const half* ChA = Ch + h * 32 + dh * 16;           // col_major (d, l), ld = CHS
        const half* ChB = Ch + 128 + h * 32 + eh * 16;     // row_major (l, e), ld = CHS
#pragma unroll
        for (int kk = 0; kk < 8; kk++) {
            wmma::fragment<wmma::matrix_a, 16, 16, 16, half, wmma::col_major> af;
            wmma::fragment<wmma::matrix_b, 16, 16, 16, half, wmma::row_major> bf;
            wmma::load_matrix_sync(af, ChA + (size_t)kk * 16 * CHS, CHS);
            wmma::load_matrix_sync(bf, ChB + (size_t)kk * 16 * CHS, CHS);
            wmma::mma_sync(sacc, af, bf, sacc);
        }
        float* Sp = g_Sp + ((size_t)(b * 4 + h) * 64 + blockIdx.x) * 1024
                  + dh * 16 * 32 + eh * 16;
        wmma::store_matrix_sync(Sp, sacc, 32, wmma::mem_row_major);
    }
}

// =====================================================================
// out GEMM (512 threads): out[128-tile x 256] = x16 @ W3^T + bias.
// Pure cp.async, all 4 k-chunks prefetched (4-stage); smem-staged epilogue.
// =====================================================================
__global__ void __launch_bounds__(512) mma_out(
    const half* __restrict__ A16, const half* __restrict__ B,
    float* __restrict__ C, const float* __restrict__ bias)
{
    extern __shared__ unsigned char smem_raw[];
    float* Cs = reinterpret_cast<float*>(smem_raw);
    const u32 sbase = smem_u32(smem_raw);

    const int tid = threadIdx.x;
    const int wid = tid >> 5;
    const int wm = wid >> 2;
    const int wn = wid & 3;
    const int b = blockIdx.y;
    const int l0 = blockIdx.x * 128;

    const half* AB = A16 + (size_t)b * NL * 256 + (size_t)l0 * 256;
    const half* BB = B + (size_t)b * 65536;

    wmma::fragment<wmma::accumulator, 16, 16, 16, float> acc[2][4];
#pragma unroll
    for (int mi = 0; mi < 2; mi++)
#pragma unroll
        for (int ni = 0; ni < 4; ni++) wmma::fill_fragment(acc[mi][ni], 0.0f);

#pragma unroll
    for (int it = 0; it < 4; it++) {
        const int k0 = it * 64;
        const u32 s0 = sbase + it * SZ_ST;
#pragma unroll
        for (int i = 0; i < 2; i++) {
            int idx = tid + i * 512;
            int row = idx >> 3, seg = idx & 7;
            cp16(s0 + O_A + (u32)(row * 144 + seg * 16), AB + (size_t)row * 256 + k0 + seg * 8);
        }
#pragma unroll
        for (int i = 0; i < 4; i++) {
            int idx = tid + i * 512;
            int n = idx >> 3, seg = idx & 7;
            cp16(s0 + O_B + (u32)(n * 144 + seg * 16), BB + (size_t)n * 256 + k0 + seg * 8);
        }
        cp_commit();
    }

    for (int it = 0; it < 4; it++) {
        if (it == 0) cp_wait<3>();
        else if (it == 1) cp_wait<2>();
        else if (it == 2) cp_wait<1>();
        else cp_wait<0>();
        __syncthreads();

        const half* Ah = (const half*)(smem_raw + it * SZ_ST + O_A);
        const half* Bs = (const half*)(smem_raw + it * SZ_ST + O_B);

#pragma unroll
        for (int kk = 0; kk < 4; kk++) {
            wmma::fragment<wmma::matrix_a, 16, 16, 16, half, wmma::row_major> ah[2];
            wmma::fragment<wmma::matrix_b, 16, 16, 16, half, wmma::col_major> bf[4];
#pragma unroll
            for (int mi = 0; mi < 2; mi++)
                wmma::load_matrix_sync(ah[mi], Ah + (wm * 32 + mi * 16) * RS + kk * 16, RS);
#pragma unroll
            for (int ni = 0; ni < 4; ni++)
                wmma::load_matrix_sync(bf[ni], Bs + (wn * 64 + ni * 16) * RS + kk * 16, RS);
#pragma unroll
            for (int mi = 0; mi < 2; mi++)
#pragma unroll
                for (int ni = 0; ni < 4; ni++)
                    wmma::mma_sync(acc[mi][ni], ah[mi], bf[ni], acc[mi][ni]);
        }
    }
    __syncthreads();

#pragma unroll
    for (int mi = 0; mi < 2; mi++)
#pragma unroll
        for (int ni = 0; ni < 4; ni++)
            wmma::store_matrix_sync(Cs + (size_t)(wm * 32 + mi * 16) * 256 + wn * 64 + ni * 16,
                                    acc[mi][ni], 256, wmma::mem_row_major);
    __syncthreads();

    float* Cb = C + (size_t)b * NL * 256 + (size_t)l0 * 256;
#pragma unroll
    for (int i = 0; i < 16; i++) {
        int idx = tid + i * 512;
        int row = idx >> 6, c4 = idx & 63;
        float4 v = *(const float4*)(Cs + (size_t)row * 256 + c4 * 4);
        float4 bb = __ldg((const float4*)(bias + c4 * 4));
        v.x += bb.x; v.y += bb.y; v.z += bb.z; v.w += bb.w;
        *(float4*)(Cb + (size_t)row * 256 + c4 * 4) = v;
    }
}

// ---------------- prep: Wkv^T fp16 ----------------
__global__ void prep_w1(const float* __restrict__ Wqkv)
{
    const int n = blockIdx.x, k = threadIdx.x;
    g_W1[n * 256 + k] = __float2half_rn(Wqkv[k * QKV_LD + 128 + n]);
}

// ---------------- fused: ctx (reduce partials) + M[b] rows for one head ----------------
__global__ void __launch_bounds__(1024) ctxm_kernel(const float* __restrict__ Wout)
{
    const int b = blockIdx.x, h = blockIdx.y;
    const int t = threadIdx.x;
    const int d = t >> 5, e = t & 31;
    __shared__ float ctx_sm[1024];
    __shared__ float zs[32];

    const float* Sp = g_Sp + (size_t)(b * 4 + h) * 64 * 1024;
    float s = 0.f;
#pragma unroll
    for (int sp = 0; sp < 64; sp++) s += Sp[sp * 1024 + t];
    if (e == 0) {
        const float* Zp = g_Zp + (size_t)(b * 4 + h) * 64 * 32;
        float zz = 0.f;
#pragma unroll
        for (int sp = 0; sp < 64; sp++) zz += Zp[sp * 32 + d];
        zs[d] = zz;
    }
    __syncthreads();
    ctx_sm[t] = s / zs[d];
    __syncthreads();

    const int j = t & 255, dg = t >> 8;
    float w[32];
#pragma unroll
    for (int e2 = 0; e2 < 32; e2++) w[e2] = Wout[(h * 32 + e2) * 256 + j];
    float* Mb = g_M + (size_t)b * HID * ND;
#pragma unroll
    for (int dd = 0; dd < 8; dd++) {
        int d2 = dg * 8 + dd;
        float a = 0.f;
#pragma unroll
        for (int e2 = 0; e2 < 32; e2++) a += ctx_sm[d2 * 32 + e2] * w[e2];
        Mb[(h * 32 + d2) * 256 + j] = a;
    }
}

// ---------------- small fp32 GEMM, 64x64 tiles (256 CTAs): writes N^T fp16 ----------------
__global__ void __launch_bounds__(256) gemm_nt(
    const float* __restrict__ A, int lda,
    const float* __restrict__ B, int ldb,
    half* __restrict__ W3, float scale)
{
    const int b = blockIdx.z;
    const int r0 = blockIdx.y * 64;
    const int n0 = blockIdx.x * 64;
    A += (size_t)r0 * lda;
    B += (size_t)b * HID * ND;

    __shared__ float As[16][64];
    __shared__ float Bs[16][64];
    const int tid = threadIdx.x;
    const int tx = tid & 15;
    const int ty = tid >> 4;

    ull acc[4][2];
#pragma unroll
    for (int m = 0; m < 4; m++) { acc[m][0] = 0ULL; acc[m][1] = 0ULL; }

    for (int k0 = 0; k0 < HID; k0 += 16) {
        {
            int row = tid >> 2, c4 = (tid & 3) * 4;
            float4 av = *(const float4*)(A + (size_t)row * lda + k0 + c4);
            As[c4 + 0][row] = av.x; As[c4 + 1][row] = av.y;
            As[c4 + 2][row] = av.z; As[c4 + 3][row] = av.w;
            int brow = tid >> 4, bc = (tid & 15) * 4;
            *(float4*)(&Bs[brow][bc]) = *(const float4*)(B + (size_t)(k0 + brow) * ldb + n0 + bc);
        }
        __syncthreads();
#pragma unroll
        for (int kk = 0; kk < 16; kk++) {
            float4 a0 = *(const float4*)(&As[kk][ty * 4]);
            float4 b0 = *(const float4*)(&Bs[kk][tx * 4]);
            ull bp0 = pk2(b0.x, b0.y), bp1 = pk2(b0.z, b0.w);
            float am[4] = { a0.x, a0.y, a0.z, a0.w };
#pragma unroll
            for (int m = 0; m < 4; m++) {
                ull ap = pk2(am[m], am[m]);
                acc[m][0] = fma2(ap, bp0, acc[m][0]);
                acc[m][1] = fma2(ap, bp1, acc[m][1]);
            }
        }
        __syncthreads();
    }

    float c[4][4];
#pragma unroll
    for (int m = 0; m < 4; m++) {
        upk2(acc[m][0], c[m][0], c[m][1]);
        upk2(acc[m][1], c[m][2], c[m][3]);
    }
    half* W = W3 + (size_t)b * 65536;
#pragma unroll
    for (int jj = 0; jj < 4; jj++) {
        int j = n0 + tx * 4 + jj;
        half2 p0 = __halves2half2(__float2half_rn(c[0][jj] * scale),
                                  __float2half_rn(c[1][jj] * scale));
        half2 p1 = __halves2half2(__float2half_rn(c[2][jj] * scale),
                                  __float2half_rn(c[3][jj] * scale));
        uint2 u = make_uint2(*(u32*)&p0, *(u32*)&p1);
        *(uint2*)(W + (size_t)j * 256 + r0 + ty * 4) = u;
    }
}

// ---------------- launch ----------------
extern "C" void kernel_launch(void* const* d_in, const int* in_sizes, int n_in,
                              void* d_out, int out_size)
{
    const float* x    = (const float*)d_in[0];
    const float* Wqkv = (const float*)d_in[1];
    const float* Wout = (const float*)d_in[2];
    const float* bout = (const float*)d_in[3];
    float* out = (float*)d_out;

    float* Mp;
    half *w1, *w3, *x16;
    cudaGetSymbolAddress((void**)&Mp, g_M);
    cudaGetSymbolAddress((void**)&w1, g_W1);
    cudaGetSymbolAddress((void**)&w3, g_W3);
    cudaGetSymbolAddress((void**)&x16, g_X16);

    cudaFuncSetAttribute(mma_kv, cudaFuncAttributeMaxDynamicSharedMemorySize, SMEM_KV);
    cudaFuncSetAttribute(mma_out, cudaFuncAttributeMaxDynamicSharedMemorySize, SMEM_OUT);

    const float scale = 0.17677669529663687f;

    // 1) Wkv^T fp16
    prep_w1<<<256, 256>>>(Wqkv);

    // 2) kv GEMM + x16 emit + fused exp/S/Z (512 threads)
    mma_kv<<<dim3(64, NB), 512, SMEM_KV>>>(x, w1, x16);

    // 3) fused ctx + M
    ctxm_kernel<<<dim3(NB, NH), 1024>>>(Wout);

    // 4) N^T fp16 = (scale * Wq @ M[b])^T
    gemm_nt<<<dim3(4, 4, NB), 256>>>(Wqkv, QKV_LD, Mp, ND, w3, scale);

    // 5) out = x16 @ N[b] + b_out (512 threads, 4-stage prefetch)
    mma_out<<<dim3(64, NB), 512, SMEM_OUT>>>(x16, w3, out, bout);
}